// round 1
// baseline (speedup 1.0000x reference)
#include <cuda_runtime.h>
#include <math.h>

#define B_ 4
#define N_ 4096
#define D_ 256
#define K_ 32
#define INV_T 14.285714285714285714f   // 1 / 0.07

#define BM 64
#define BN 128
#define BK 32
#define ASP 68    // padded row length of transposed A tile  [BK][ASP]
#define BSP 132   // padded row length of transposed B tile  [BK][BSP]
#define SCP 132   // padded row length of score tile         [BM][SCP]

// scratch for normalized features (16 MB each)
__device__ float g_f1n[B_ * N_ * D_];
__device__ float g_f2n[B_ * N_ * D_];

// ---------------------------------------------------------------------------
// Row L2 normalization: one warp per row (D=256 -> 8 floats/lane via 2x float4)
// ---------------------------------------------------------------------------
__global__ void normalize_kernel(const float* __restrict__ F1,
                                 const float* __restrict__ F2) {
    int gw   = (blockIdx.x * blockDim.x + threadIdx.x) >> 5;
    int lane = threadIdx.x & 31;
    const int R = B_ * N_;
    if (gw >= 2 * R) return;

    const float* src;
    float* dst;
    int row;
    if (gw < R) { src = F1; dst = g_f1n; row = gw; }
    else        { src = F2; dst = g_f2n; row = gw - R; }

    const float4* s4 = (const float4*)(src + (size_t)row * D_);
    float4* d4 = (float4*)(dst + (size_t)row * D_);

    float4 v0 = s4[lane];
    float4 v1 = s4[lane + 32];
    float ss = v0.x * v0.x + v0.y * v0.y + v0.z * v0.z + v0.w * v0.w
             + v1.x * v1.x + v1.y * v1.y + v1.z * v1.z + v1.w * v1.w;
#pragma unroll
    for (int o = 16; o; o >>= 1) ss += __shfl_xor_sync(0xffffffffu, ss, o);

    float inv = 1.0f / fmaxf(sqrtf(ss), 1e-12f);

    v0.x *= inv; v0.y *= inv; v0.z *= inv; v0.w *= inv;
    v1.x *= inv; v1.y *= inv; v1.z *= inv; v1.w *= inv;
    d4[lane]      = v0;
    d4[lane + 32] = v1;
}

// ---------------------------------------------------------------------------
// Sorted-descending top-K insert (stable: equal values keep lower index first,
// because columns are scanned in ascending order and insert uses strict >)
// ---------------------------------------------------------------------------
__device__ __forceinline__ void insert_topk(float* tv, int* ti, float v, int idx) {
    int pos = K_ - 1;
    while (pos > 0 && tv[pos - 1] < v) {
        tv[pos] = tv[pos - 1];
        ti[pos] = ti[pos - 1];
        pos--;
    }
    tv[pos] = v;
    ti[pos] = idx;
}

// ---------------------------------------------------------------------------
// Fused fp32 GEMM (64x4096 rows-block, col tiles of 128) + running top-32 +
// softmax + scatter. Grid: (N_/BM, B_). 256 threads (8 warps), thread tile 8x4.
// ---------------------------------------------------------------------------
__global__ __launch_bounds__(256, 1) void gemm_topk_kernel(float* __restrict__ out) {
    extern __shared__ float sm[];
    float* As   = sm;                       // [BK][ASP]  2176 floats
    float* Bs   = As + BK * ASP;            // [BK][BSP]  4224 floats
    float* Sc   = Bs + BK * BSP;            // [BM][SCP]  8448 floats
    float* topv = Sc + BM * SCP;            // [BM][K_]   2048 floats
    int*   topi = (int*)(topv + BM * K_);   // [BM][K_]   2048 ints

    const int tid = threadIdx.x;
    const int tx = tid & 31;      // lane -> 32 col groups of 4
    const int ty = tid >> 5;      // warp -> 8 row groups of 8
    const int b  = blockIdx.y;
    const int n0 = blockIdx.x * BM;

    for (int i = tid; i < BM * K_; i += 256) {
        topv[i] = -3.4e38f;
        topi[i] = 0;
    }
    __syncthreads();

    const float* A  = g_f1n + ((size_t)b * N_ + n0) * D_;
    const float* Bt = g_f2n + (size_t)b * N_ * D_;

    for (int m0 = 0; m0 < N_; m0 += BN) {
        float acc[8][4];
#pragma unroll
        for (int i = 0; i < 8; i++)
#pragma unroll
            for (int j = 0; j < 4; j++) acc[i][j] = 0.0f;

        for (int k0 = 0; k0 < D_; k0 += BK) {
            // Fill As transposed: 64 rows x 32 k  (512 float4 loads)
#pragma unroll
            for (int it = 0; it < 2; it++) {
                int lin = tid + it * 256;
                int r = lin >> 3, c = lin & 7;
                float4 v = *(const float4*)(A + (size_t)r * D_ + k0 + c * 4);
                As[(c * 4 + 0) * ASP + r] = v.x;
                As[(c * 4 + 1) * ASP + r] = v.y;
                As[(c * 4 + 2) * ASP + r] = v.z;
                As[(c * 4 + 3) * ASP + r] = v.w;
            }
            // Fill Bs transposed: 128 cols x 32 k (1024 float4 loads)
#pragma unroll
            for (int it = 0; it < 4; it++) {
                int lin = tid + it * 256;
                int r = lin >> 3, c = lin & 7;
                float4 v = *(const float4*)(Bt + (size_t)(m0 + r) * D_ + k0 + c * 4);
                Bs[(c * 4 + 0) * BSP + r] = v.x;
                Bs[(c * 4 + 1) * BSP + r] = v.y;
                Bs[(c * 4 + 2) * BSP + r] = v.z;
                Bs[(c * 4 + 3) * BSP + r] = v.w;
            }
            __syncthreads();

#pragma unroll
            for (int kk = 0; kk < BK; kk++) {
                float4 a0 = *(const float4*)(As + kk * ASP + ty * 8);
                float4 a1 = *(const float4*)(As + kk * ASP + ty * 8 + 4);
                float4 bb = *(const float4*)(Bs + kk * BSP + tx * 4);
                float av[8] = {a0.x, a0.y, a0.z, a0.w, a1.x, a1.y, a1.z, a1.w};
                float bv[4] = {bb.x, bb.y, bb.z, bb.w};
#pragma unroll
                for (int i = 0; i < 8; i++)
#pragma unroll
                    for (int j = 0; j < 4; j++)
                        acc[i][j] = fmaf(av[i], bv[j], acc[i][j]);
            }
            __syncthreads();
        }

        // Dump score tile to smem
#pragma unroll
        for (int i = 0; i < 8; i++) {
            *(float4*)(Sc + (size_t)(ty * 8 + i) * SCP + tx * 4) =
                make_float4(acc[i][0], acc[i][1], acc[i][2], acc[i][3]);
        }
        __syncthreads();

        // Per-row running top-K (one thread per row; inserts are rare)
        if (tid < BM) {
            float* tv = topv + tid * K_;
            int*   ti = topi + tid * K_;
            const float* sr = Sc + (size_t)tid * SCP;
            float tmin = tv[K_ - 1];
            for (int j = 0; j < BN; j += 4) {
                float v0 = sr[j + 0];
                float v1 = sr[j + 1];
                float v2 = sr[j + 2];
                float v3 = sr[j + 3];
                if (v0 > tmin) { insert_topk(tv, ti, v0, m0 + j + 0); tmin = tv[K_ - 1]; }
                if (v1 > tmin) { insert_topk(tv, ti, v1, m0 + j + 1); tmin = tv[K_ - 1]; }
                if (v2 > tmin) { insert_topk(tv, ti, v2, m0 + j + 2); tmin = tv[K_ - 1]; }
                if (v3 > tmin) { insert_topk(tv, ti, v3, m0 + j + 3); tmin = tv[K_ - 1]; }
            }
        }
        __syncthreads();
    }

    // Softmax over top-K and scatter
    if (tid < BM) {
        const int n = n0 + tid;
        float* tv = topv + tid * K_;
        int*   ti = topi + tid * K_;
        float mx = tv[0];
        float e[K_];
        float s = 0.0f;
#pragma unroll
        for (int k = 0; k < K_; k++) {
            e[k] = expf((tv[k] - mx) * INV_T);
            s += e[k];
        }
        float inv = 1.0f / s;
        size_t rowbase = ((size_t)b * N_ + n) * N_;
        size_t idxbase = (size_t)B_ * N_ * N_ + ((size_t)b * N_ + n) * K_;
#pragma unroll
        for (int k = 0; k < K_; k++) {
            out[rowbase + (size_t)ti[k]] = e[k] * inv;
            out[idxbase + k] = (float)ti[k];
        }
    }
}

// ---------------------------------------------------------------------------
extern "C" void kernel_launch(void* const* d_in, const int* in_sizes, int n_in,
                              void* d_out, int out_size) {
    const float* F1 = (const float*)d_in[0];
    const float* F2 = (const float*)d_in[1];
    float* out = (float*)d_out;

    // Zero the soft_corr region (idx region is fully overwritten)
    cudaMemsetAsync(out, 0, (size_t)B_ * N_ * N_ * sizeof(float), 0);

    normalize_kernel<<<4096, 256>>>(F1, F2);

    const int smem_bytes = (BK * ASP + BK * BSP + BM * SCP + BM * K_ * 2) * 4; // 75776
    cudaFuncSetAttribute(gemm_topk_kernel,
                         cudaFuncAttributeMaxDynamicSharedMemorySize, smem_bytes);
    gemm_topk_kernel<<<dim3(N_ / BM, B_), 256, smem_bytes>>>(out);
}

// round 7
// speedup vs baseline: 1.0395x; 1.0395x over previous
#include <cuda_runtime.h>
#include <cuda_bf16.h>
#include <stdint.h>
#include <math.h>

#define B_ 4
#define N_ 4096
#define D_ 256
#define K_ 32
#define NC 40                    // HMMA candidate count (superset of top-32)
#define KTOT 768
#define INV_T 14.285714285714285714f

#define TILE_M 128
#define TILE_N 128
#define NKSTAGE 12               // KTOT / 64
#define NCTILE 32                // N_ / TILE_N
#define GS_TOTAL (NCTILE * NKSTAGE)   // 384
#define A_BYTES (TILE_M * 128)   // 16384
#define B_BYTES (TILE_N * 128)   // 16384
#define STAGE_BYTES (A_BYTES + B_BYTES)  // 32768
#define SCP 130

// smem map (dynamic)
#define SC_OFF (3 * STAGE_BYTES)                  // 98304
#define TV_OFF (SC_OFF + TILE_M * SCP * 4)        // 164864
#define TI_OFF (TV_OFF + TILE_M * NC * 4)         // 185344
#define SMEM_TOTAL (TI_OFF + TILE_M * NC * 4)     // 205824

// split features: A' = [hi1 | hi1 | lo1], B' = [hi2 | lo2 | hi2]  -> K=768
__device__ __nv_bfloat16 g_a[(size_t)B_ * N_ * KTOT];
__device__ __nv_bfloat16 g_b[(size_t)B_ * N_ * KTOT];
// exact fp32 normalized features (for candidate rescoring)
__device__ float g_f1n[(size_t)B_ * N_ * D_];
__device__ float g_f2n[(size_t)B_ * N_ * D_];

// ---------------------------------------------------------------------------
__device__ __forceinline__ uint32_t smem_u32(const void* p) {
    uint32_t a;
    asm("{ .reg .u64 t; cvta.to.shared.u64 t, %1; cvt.u32.u64 %0, t; }" : "=r"(a) : "l"(p));
    return a;
}
__device__ __forceinline__ void cp16(uint32_t dst, const void* src) {
    asm volatile("cp.async.cg.shared.global [%0], [%1], 16;" :: "r"(dst), "l"(src));
}
#define CP_COMMIT() asm volatile("cp.async.commit_group;" ::: "memory")
#define CP_WAIT1()  asm volatile("cp.async.wait_group 1;" ::: "memory")

__device__ __forceinline__ uint32_t swz(uint32_t x) { return x ^ ((x >> 3) & 0x70); }

__device__ __forceinline__ void ldsm4(uint32_t* r, uint32_t addr) {
    asm volatile("ldmatrix.sync.aligned.m8n8.x4.shared.b16 {%0,%1,%2,%3}, [%4];"
                 : "=r"(r[0]), "=r"(r[1]), "=r"(r[2]), "=r"(r[3]) : "r"(addr));
}
__device__ __forceinline__ void hmma(float* c, const uint32_t* a, const uint32_t* b) {
    asm volatile(
        "mma.sync.aligned.m16n8k16.row.col.f32.bf16.bf16.f32 "
        "{%0,%1,%2,%3}, {%4,%5,%6,%7}, {%8,%9}, {%0,%1,%2,%3};"
        : "+f"(c[0]), "+f"(c[1]), "+f"(c[2]), "+f"(c[3])
        : "r"(a[0]), "r"(a[1]), "r"(a[2]), "r"(a[3]), "r"(b[0]), "r"(b[1]));
}

// ---------------------------------------------------------------------------
// normalize (fp32, division like jax) + hi/lo bf16 split
// ---------------------------------------------------------------------------
__global__ void normalize_split_kernel(const float* __restrict__ F1,
                                       const float* __restrict__ F2) {
    int gw = (blockIdx.x * blockDim.x + threadIdx.x) >> 5;
    int lane = threadIdx.x & 31;
    const int R = B_ * N_;
    if (gw >= 2 * R) return;

    const float* src;
    __nv_bfloat16* dst;
    float* fdst;
    int row, isA;
    if (gw < R) { src = F1; dst = g_a; fdst = g_f1n; row = gw; isA = 1; }
    else        { src = F2; dst = g_b; fdst = g_f2n; row = gw - R; isA = 0; }

    const float4* s4 = (const float4*)(src + (size_t)row * D_);
    float4 v0 = s4[lane];
    float4 v1 = s4[lane + 32];
    float ss = v0.x*v0.x + v0.y*v0.y + v0.z*v0.z + v0.w*v0.w
             + v1.x*v1.x + v1.y*v1.y + v1.z*v1.z + v1.w*v1.w;
#pragma unroll
    for (int o = 16; o; o >>= 1) ss += __shfl_xor_sync(0xffffffffu, ss, o);
    float nrm = fmaxf(sqrtf(ss), 1e-12f);

    float f[8] = {v0.x/nrm, v0.y/nrm, v0.z/nrm, v0.w/nrm,
                  v1.x/nrm, v1.y/nrm, v1.z/nrm, v1.w/nrm};

    // exact fp32 normalized
    float4* o4 = (float4*)(fdst + (size_t)row * D_);
    o4[lane]      = make_float4(f[0], f[1], f[2], f[3]);
    o4[lane + 32] = make_float4(f[4], f[5], f[6], f[7]);

    __nv_bfloat16* rp = dst + (size_t)row * KTOT;
#pragma unroll
    for (int i = 0; i < 8; i++) {
        int c = (i < 4) ? (lane * 4 + i) : (128 + lane * 4 + i - 4);
        __nv_bfloat16 hi = __float2bfloat16_rn(f[i]);
        __nv_bfloat16 lo = __float2bfloat16_rn(f[i] - __bfloat162float(hi));
        if (isA) { rp[c] = hi; rp[256 + c] = hi; rp[512 + c] = lo; }
        else     { rp[c] = hi; rp[256 + c] = lo; rp[512 + c] = hi; }
    }
}

// ---------------------------------------------------------------------------
// running candidate insert (sorted desc, strict > keeps lower index on ties)
// ---------------------------------------------------------------------------
__device__ __forceinline__ void insert_cand(float* tv, int* ti, float v, int idx) {
    int pos = NC - 1;
    while (pos > 0 && tv[pos - 1] < v) {
        tv[pos] = tv[pos - 1];
        ti[pos] = ti[pos - 1];
        pos--;
    }
    tv[pos] = v;
    ti[pos] = idx;
}
// final stable top-K insert: desc value, ascending index on exact ties (jax)
__device__ __forceinline__ void insert_final(float* tv, int* ti, float v, int idx) {
    int pos = K_ - 1;
    while (pos > 0 && (tv[pos - 1] < v || (tv[pos - 1] == v && ti[pos - 1] > idx))) {
        tv[pos] = tv[pos - 1];
        ti[pos] = ti[pos - 1];
        pos--;
    }
    tv[pos] = v;
    ti[pos] = idx;
}

// issue cp.async group for pipeline stage gs (buffer gs%3)
__device__ __forceinline__ void issue_stage(uint32_t sbase, int gs,
                                            const char* gA, const char* gB, int tid) {
    const int t = gs / NKSTAGE;
    const int s = gs - t * NKSTAGE;
    const uint32_t base = sbase + (gs % 3) * STAGE_BYTES;
    const int kb = s * 128;
    const char* bsrc = gB + (size_t)t * TILE_N * (KTOT * 2);
#pragma unroll
    for (int i = 0; i < 4; i++) {
        int ch = i * 256 + tid;
        int r = ch >> 3, c = ch & 7;
        cp16(base + swz(r * 128 + c * 16), gA + (size_t)r * (KTOT * 2) + kb + c * 16);
    }
#pragma unroll
    for (int i = 0; i < 4; i++) {
        int ch = i * 256 + tid;
        int r = ch >> 3, c = ch & 7;
        cp16(base + A_BYTES + swz(r * 128 + c * 16),
             bsrc + (size_t)r * (KTOT * 2) + kb + c * 16);
    }
    CP_COMMIT();
}

// ---------------------------------------------------------------------------
// fused HMMA GEMM + top-40 candidates + exact fp32 rescore + top-32 + scatter
// grid (32, 4), 256 threads (8 warps: 4m x 2n), warp tile 32x64
// ---------------------------------------------------------------------------
__global__ __launch_bounds__(256, 1) void gemm_topk_hmma(float* __restrict__ out) {
    extern __shared__ char smem[];
    const uint32_t sbase = smem_u32(smem);
    float* Sc   = (float*)(smem + SC_OFF);
    float* topv = (float*)(smem + TV_OFF);
    int*   topi = (int*)(smem + TI_OFF);

    const int tid  = threadIdx.x;
    const int wid  = tid >> 5;
    const int lane = tid & 31;
    const int wm   = wid & 3;
    const int wn   = wid >> 2;
    const int bb   = blockIdx.y;
    const int m0   = blockIdx.x * TILE_M;

    for (int i = tid; i < TILE_M * NC; i += 256) {
        topv[i] = -3.4e38f;
        topi[i] = 0;
    }

    const char* gA = (const char*)g_a + ((size_t)(bb * N_ + m0) * KTOT) * 2;
    const char* gB = (const char*)g_b + ((size_t)bb * N_ * KTOT) * 2;

    const int g  = lane >> 3;
    const int lr = lane & 7;
    const uint32_t aoff = (uint32_t)((wm * 32 + (g & 1) * 8 + lr) * 128 + (g >> 1) * 16);
    const uint32_t boff = (uint32_t)((wn * 64 + (g >> 1) * 8 + lr) * 128 + (g & 1) * 16);

    issue_stage(sbase, 0, gA, gB, tid);
    issue_stage(sbase, 1, gA, gB, tid);

    for (int t = 0; t < NCTILE; ++t) {
        float C[2][8][4];
#pragma unroll
        for (int mt = 0; mt < 2; mt++)
#pragma unroll
            for (int nt = 0; nt < 8; nt++)
#pragma unroll
                for (int e = 0; e < 4; e++) C[mt][nt][e] = 0.0f;

        for (int s = 0; s < NKSTAGE; ++s) {
            const int gs = t * NKSTAGE + s;
            CP_WAIT1();
            __syncthreads();
            if (gs + 2 < GS_TOTAL) issue_stage(sbase, gs + 2, gA, gB, tid);
            else CP_COMMIT();

            const uint32_t sA = sbase + (gs % 3) * STAGE_BYTES;
            const uint32_t sB = sA + A_BYTES;
#pragma unroll
            for (int kk = 0; kk < 4; kk++) {
                uint32_t a0[4], a1[4], b[4][4];
                ldsm4(a0, sA + swz(aoff + kk * 32));
                ldsm4(a1, sA + swz(aoff + 2048 + kk * 32));
#pragma unroll
                for (int p = 0; p < 4; p++)
                    ldsm4(b[p], sB + swz(boff + p * 2048 + kk * 32));
#pragma unroll
                for (int p = 0; p < 4; p++) {
                    hmma(C[0][2 * p + 0], a0, &b[p][0]);
                    hmma(C[0][2 * p + 1], a0, &b[p][2]);
                    hmma(C[1][2 * p + 0], a1, &b[p][0]);
                    hmma(C[1][2 * p + 1], a1, &b[p][2]);
                }
            }
        }

        __syncthreads();
#pragma unroll
        for (int mt = 0; mt < 2; mt++) {
            const int r0 = wm * 32 + mt * 16 + (lane >> 2);
            const int c0 = wn * 64 + 2 * (lane & 3);
#pragma unroll
            for (int nt = 0; nt < 8; nt++) {
                const int c = c0 + nt * 8;
                *(float2*)(Sc + r0 * SCP + c) = make_float2(C[mt][nt][0], C[mt][nt][1]);
                *(float2*)(Sc + (r0 + 8) * SCP + c) = make_float2(C[mt][nt][2], C[mt][nt][3]);
            }
        }
        __syncthreads();

        if (tid < TILE_M) {
            float* tv = topv + tid * NC;
            int*   ti = topi + tid * NC;
            const float* sr = Sc + tid * SCP;
            const int cb = t * TILE_N;
            float tmin = tv[NC - 1];
            for (int j = 0; j < TILE_N; j += 4) {
                float v0 = sr[j + 0], v1 = sr[j + 1], v2 = sr[j + 2], v3 = sr[j + 3];
                if (v0 > tmin) { insert_cand(tv, ti, v0, cb + j + 0); tmin = tv[NC - 1]; }
                if (v1 > tmin) { insert_cand(tv, ti, v1, cb + j + 1); tmin = tv[NC - 1]; }
                if (v2 > tmin) { insert_cand(tv, ti, v2, cb + j + 2); tmin = tv[NC - 1]; }
                if (v3 > tmin) { insert_cand(tv, ti, v3, cb + j + 3); tmin = tv[NC - 1]; }
            }
        }
        __syncthreads();
    }

    // ---------------- exact fp32 rescore of the NC candidates ----------------
    // warp w handles rows [w*16, w*16+16); warp-cooperative dot per candidate
    {
        const float* f1b = g_f1n + ((size_t)(bb * N_ + m0)) * D_;
        const float* f2b = g_f2n + (size_t)bb * N_ * D_;
        for (int r = wid * 16; r < wid * 16 + 16; ++r) {
            const float4* a4 = (const float4*)(f1b + (size_t)r * D_);
            float4 a0 = a4[lane], a1 = a4[lane + 32];
#pragma unroll 2
            for (int c = 0; c < NC; ++c) {
                int col = topi[r * NC + c];
                const float4* b4 = (const float4*)(f2b + (size_t)col * D_);
                float4 b0 = b4[lane], b1 = b4[lane + 32];
                float s = a0.x * b0.x;
                s = fmaf(a0.y, b0.y, s);
                s = fmaf(a0.z, b0.z, s);
                s = fmaf(a0.w, b0.w, s);
                s = fmaf(a1.x, b1.x, s);
                s = fmaf(a1.y, b1.y, s);
                s = fmaf(a1.z, b1.z, s);
                s = fmaf(a1.w, b1.w, s);
#pragma unroll
                for (int o = 16; o; o >>= 1) s += __shfl_xor_sync(0xffffffffu, s, o);
                if (lane == 0) topv[r * NC + c] = s;   // overwrite with exact score
            }
        }
    }
    __syncthreads();

    // ---------------- final stable top-32 + softmax + scatter ----------------
    if (tid < TILE_M) {
        const int n = m0 + tid;
        const float* cv = topv + tid * NC;
        const int*   ci = topi + tid * NC;
        float tv[K_];
        int ti[K_];
#pragma unroll
        for (int k = 0; k < K_; k++) { tv[k] = -3.4e38f; ti[k] = 0x7fffffff; }
#pragma unroll
        for (int c = 0; c < NC; c++) {
            float v = cv[c];
            int idx = ci[c];
            float wv = tv[K_ - 1];
            if (v > wv || (v == wv && idx < ti[K_ - 1]))
                insert_final(tv, ti, v, idx);
        }
        float mx = tv[0];
        float e[K_];
        float s = 0.0f;
#pragma unroll
        for (int k = 0; k < K_; k++) { e[k] = expf((tv[k] - mx) * INV_T); s += e[k]; }
        float inv = 1.0f / s;
        size_t rowbase = ((size_t)bb * N_ + n) * N_;
        size_t idxbase = (size_t)B_ * N_ * N_ + ((size_t)bb * N_ + n) * K_;
#pragma unroll
        for (int k = 0; k < K_; k++) {
            out[rowbase + (size_t)ti[k]] = e[k] * inv;
            out[idxbase + k] = (float)ti[k];
        }
    }
}

// ---------------------------------------------------------------------------
extern "C" void kernel_launch(void* const* d_in, const int* in_sizes, int n_in,
                              void* d_out, int out_size) {
    const float* F1 = (const float*)d_in[0];
    const float* F2 = (const float*)d_in[1];
    float* out = (float*)d_out;

    cudaMemsetAsync(out, 0, (size_t)B_ * N_ * N_ * sizeof(float), 0);
    normalize_split_kernel<<<4096, 256>>>(F1, F2);

    cudaFuncSetAttribute(gemm_topk_hmma,
                         cudaFuncAttributeMaxDynamicSharedMemorySize, SMEM_TOTAL);
    gemm_topk_hmma<<<dim3(NCTILE, B_), 256, SMEM_TOTAL>>>(out);
}

// round 8
// speedup vs baseline: 1.1914x; 1.1461x over previous
#include <cuda_runtime.h>
#include <cuda_bf16.h>
#include <stdint.h>
#include <math.h>

#define B_ 4
#define N_ 4096
#define D_ 256
#define K_ 32
#define NC 40                    // HMMA candidate count (superset of top-32)
#define KTOT 256                 // hi-only bf16 selection GEMM
#define INV_T 14.285714285714285714f

#define TILE_M 128
#define TILE_N 128
#define NKSTAGE 4                // KTOT / 64
#define NCTILE 32                // N_ / TILE_N
#define GS_TOTAL (NCTILE * NKSTAGE)   // 128
#define A_BYTES (TILE_M * 128)   // 16384
#define B_BYTES (TILE_N * 128)   // 16384
#define STAGE_BYTES (A_BYTES + B_BYTES)  // 32768
#define SCP 130
#define NTHREADS 512

// smem map (dynamic)
#define SC_OFF (3 * STAGE_BYTES)                  // 98304
#define TV_OFF (SC_OFF + TILE_M * SCP * 4)        // 164864
#define TI_OFF (TV_OFF + TILE_M * NC * 4)         // 185344
#define SMEM_TOTAL (TI_OFF + TILE_M * NC * 4)     // 205824

// hi-only bf16 normalized features
__device__ __nv_bfloat16 g_a[(size_t)B_ * N_ * KTOT];
__device__ __nv_bfloat16 g_b[(size_t)B_ * N_ * KTOT];
// exact fp32 normalized features (for candidate rescoring)
__device__ float g_f1n[(size_t)B_ * N_ * D_];
__device__ float g_f2n[(size_t)B_ * N_ * D_];

// ---------------------------------------------------------------------------
__device__ __forceinline__ uint32_t smem_u32(const void* p) {
    uint32_t a;
    asm("{ .reg .u64 t; cvta.to.shared.u64 t, %1; cvt.u32.u64 %0, t; }" : "=r"(a) : "l"(p));
    return a;
}
__device__ __forceinline__ void cp16(uint32_t dst, const void* src) {
    asm volatile("cp.async.cg.shared.global [%0], [%1], 16;" :: "r"(dst), "l"(src));
}
#define CP_COMMIT() asm volatile("cp.async.commit_group;" ::: "memory")
#define CP_WAIT1()  asm volatile("cp.async.wait_group 1;" ::: "memory")

__device__ __forceinline__ uint32_t swz(uint32_t x) { return x ^ ((x >> 3) & 0x70); }

__device__ __forceinline__ void ldsm4(uint32_t* r, uint32_t addr) {
    asm volatile("ldmatrix.sync.aligned.m8n8.x4.shared.b16 {%0,%1,%2,%3}, [%4];"
                 : "=r"(r[0]), "=r"(r[1]), "=r"(r[2]), "=r"(r[3]) : "r"(addr));
}
__device__ __forceinline__ void hmma(float* c, const uint32_t* a, const uint32_t* b) {
    asm volatile(
        "mma.sync.aligned.m16n8k16.row.col.f32.bf16.bf16.f32 "
        "{%0,%1,%2,%3}, {%4,%5,%6,%7}, {%8,%9}, {%0,%1,%2,%3};"
        : "+f"(c[0]), "+f"(c[1]), "+f"(c[2]), "+f"(c[3])
        : "r"(a[0]), "r"(a[1]), "r"(a[2]), "r"(a[3]), "r"(b[0]), "r"(b[1]));
}

// ---------------------------------------------------------------------------
// normalize (fp32, division like jax) + bf16 hi cast
// ---------------------------------------------------------------------------
__global__ void normalize_split_kernel(const float* __restrict__ F1,
                                       const float* __restrict__ F2) {
    int gw = (blockIdx.x * blockDim.x + threadIdx.x) >> 5;
    int lane = threadIdx.x & 31;
    const int R = B_ * N_;
    if (gw >= 2 * R) return;

    const float* src;
    __nv_bfloat16* dst;
    float* fdst;
    int row;
    if (gw < R) { src = F1; dst = g_a; fdst = g_f1n; row = gw; }
    else        { src = F2; dst = g_b; fdst = g_f2n; row = gw - R; }

    const float4* s4 = (const float4*)(src + (size_t)row * D_);
    float4 v0 = s4[lane];
    float4 v1 = s4[lane + 32];
    float ss = v0.x*v0.x + v0.y*v0.y + v0.z*v0.z + v0.w*v0.w
             + v1.x*v1.x + v1.y*v1.y + v1.z*v1.z + v1.w*v1.w;
#pragma unroll
    for (int o = 16; o; o >>= 1) ss += __shfl_xor_sync(0xffffffffu, ss, o);
    float nrm = fmaxf(sqrtf(ss), 1e-12f);

    float f[8] = {v0.x/nrm, v0.y/nrm, v0.z/nrm, v0.w/nrm,
                  v1.x/nrm, v1.y/nrm, v1.z/nrm, v1.w/nrm};

    float4* o4 = (float4*)(fdst + (size_t)row * D_);
    o4[lane]      = make_float4(f[0], f[1], f[2], f[3]);
    o4[lane + 32] = make_float4(f[4], f[5], f[6], f[7]);

    __nv_bfloat16* rp = dst + (size_t)row * KTOT;
#pragma unroll
    for (int i = 0; i < 8; i++) {
        int c = (i < 4) ? (lane * 4 + i) : (128 + lane * 4 + i - 4);
        rp[c] = __float2bfloat16_rn(f[i]);
    }
}

// ---------------------------------------------------------------------------
__device__ __forceinline__ void insert_cand(float* tv, int* ti, float v, int idx) {
    int pos = NC - 1;
    while (pos > 0 && tv[pos - 1] < v) {
        tv[pos] = tv[pos - 1];
        ti[pos] = ti[pos - 1];
        pos--;
    }
    tv[pos] = v;
    ti[pos] = idx;
}
// final stable top-K insert: desc value, ascending index on exact ties (jax)
__device__ __forceinline__ void insert_final(float* tv, int* ti, float v, int idx) {
    int pos = K_ - 1;
    while (pos > 0 && (tv[pos - 1] < v || (tv[pos - 1] == v && ti[pos - 1] > idx))) {
        tv[pos] = tv[pos - 1];
        ti[pos] = ti[pos - 1];
        pos--;
    }
    tv[pos] = v;
    ti[pos] = idx;
}

// issue cp.async group for pipeline stage gs (buffer gs%3)
__device__ __forceinline__ void issue_stage(uint32_t sbase, int gs,
                                            const char* gA, const char* gB, int tid) {
    const int t = gs >> 2;               // tile
    const int s = gs & 3;                // k-stage within tile
    const uint32_t base = sbase + (gs % 3) * STAGE_BYTES;
    const int kb = s * 128;              // byte offset into K (64 bf16)
    const char* bsrc = gB + (size_t)t * TILE_N * (KTOT * 2);
#pragma unroll
    for (int i = 0; i < 2; i++) {        // A: 1024 16B chunks / 512 thr
        int ch = i * NTHREADS + tid;
        int r = ch >> 3, c = ch & 7;
        cp16(base + swz(r * 128 + c * 16), gA + (size_t)r * (KTOT * 2) + kb + c * 16);
    }
#pragma unroll
    for (int i = 0; i < 2; i++) {        // B: 1024 16B chunks
        int ch = i * NTHREADS + tid;
        int r = ch >> 3, c = ch & 7;
        cp16(base + A_BYTES + swz(r * 128 + c * 16),
             bsrc + (size_t)r * (KTOT * 2) + kb + c * 16);
    }
    CP_COMMIT();
}

// ---------------------------------------------------------------------------
// fused HMMA GEMM (K=256) + top-40 candidates + exact fp32 rescore + top-32
// grid (32, 4), 512 threads (16 warps: 4m x 4n), warp tile 32x32
// ---------------------------------------------------------------------------
__global__ __launch_bounds__(NTHREADS, 1) void gemm_topk_hmma(float* __restrict__ out) {
    extern __shared__ char smem[];
    const uint32_t sbase = smem_u32(smem);
    float* Sc   = (float*)(smem + SC_OFF);
    float* topv = (float*)(smem + TV_OFF);
    int*   topi = (int*)(smem + TI_OFF);

    const int tid  = threadIdx.x;
    const int wid  = tid >> 5;
    const int lane = tid & 31;
    const int wm   = wid & 3;        // 4 row groups of 32
    const int wn   = wid >> 2;       // 4 col groups of 32
    const int bb   = blockIdx.y;
    const int m0   = blockIdx.x * TILE_M;

    for (int i = tid; i < TILE_M * NC; i += NTHREADS) {
        topv[i] = -3.4e38f;
        topi[i] = 0;
    }

    const char* gA = (const char*)g_a + ((size_t)(bb * N_ + m0) * KTOT) * 2;
    const char* gB = (const char*)g_b + ((size_t)bb * N_ * KTOT) * 2;

    const int g  = lane >> 3;
    const int lr = lane & 7;
    // A tiles: [r0-7,k0-7],[r8-15,k0-7],[r0-7,k8-15],[r8-15,k8-15]
    const uint32_t aoff = (uint32_t)((wm * 32 + (g & 1) * 8 + lr) * 128 + (g >> 1) * 16);
    // B tiles: [n0-7,k0-7],[n0-7,k8-15],[n8-15,k0-7],[n8-15,k8-15]
    const uint32_t boff = (uint32_t)((wn * 32 + (g >> 1) * 8 + lr) * 128 + (g & 1) * 16);

    issue_stage(sbase, 0, gA, gB, tid);
    issue_stage(sbase, 1, gA, gB, tid);

    for (int t = 0; t < NCTILE; ++t) {
        float C[2][4][4];
#pragma unroll
        for (int mt = 0; mt < 2; mt++)
#pragma unroll
            for (int nt = 0; nt < 4; nt++)
#pragma unroll
                for (int e = 0; e < 4; e++) C[mt][nt][e] = 0.0f;

        for (int s = 0; s < NKSTAGE; ++s) {
            const int gs = t * NKSTAGE + s;
            CP_WAIT1();
            __syncthreads();
            if (gs + 2 < GS_TOTAL) issue_stage(sbase, gs + 2, gA, gB, tid);
            else CP_COMMIT();

            const uint32_t sA = sbase + (gs % 3) * STAGE_BYTES;
            const uint32_t sB = sA + A_BYTES;
#pragma unroll
            for (int kk = 0; kk < 4; kk++) {
                uint32_t a0[4], a1[4], b[2][4];
                ldsm4(a0, sA + swz(aoff + kk * 32));
                ldsm4(a1, sA + swz(aoff + 2048 + kk * 32));
#pragma unroll
                for (int p = 0; p < 2; p++)
                    ldsm4(b[p], sB + swz(boff + p * 2048 + kk * 32));
#pragma unroll
                for (int p = 0; p < 2; p++) {
                    hmma(C[0][2 * p + 0], a0, &b[p][0]);
                    hmma(C[0][2 * p + 1], a0, &b[p][2]);
                    hmma(C[1][2 * p + 0], a1, &b[p][0]);
                    hmma(C[1][2 * p + 1], a1, &b[p][2]);
                }
            }
        }

        __syncthreads();
#pragma unroll
        for (int mt = 0; mt < 2; mt++) {
            const int r0 = wm * 32 + mt * 16 + (lane >> 2);
            const int c0 = wn * 32 + 2 * (lane & 3);
#pragma unroll
            for (int nt = 0; nt < 4; nt++) {
                const int c = c0 + nt * 8;
                *(float2*)(Sc + r0 * SCP + c) = make_float2(C[mt][nt][0], C[mt][nt][1]);
                *(float2*)(Sc + (r0 + 8) * SCP + c) = make_float2(C[mt][nt][2], C[mt][nt][3]);
            }
        }
        __syncthreads();

        if (tid < TILE_M) {
            float* tv = topv + tid * NC;
            int*   ti = topi + tid * NC;
            const float* sr = Sc + tid * SCP;
            const int cb = t * TILE_N;
            float tmin = tv[NC - 1];
            for (int j = 0; j < TILE_N; j += 4) {
                float v0 = sr[j + 0], v1 = sr[j + 1], v2 = sr[j + 2], v3 = sr[j + 3];
                if (v0 > tmin) { insert_cand(tv, ti, v0, cb + j + 0); tmin = tv[NC - 1]; }
                if (v1 > tmin) { insert_cand(tv, ti, v1, cb + j + 1); tmin = tv[NC - 1]; }
                if (v2 > tmin) { insert_cand(tv, ti, v2, cb + j + 2); tmin = tv[NC - 1]; }
                if (v3 > tmin) { insert_cand(tv, ti, v3, cb + j + 3); tmin = tv[NC - 1]; }
            }
        }
        __syncthreads();
    }

    // ---------------- exact fp32 rescore of the NC candidates ----------------
    // warp w handles rows [w*8, w*8+8); warp-cooperative dot per candidate
    {
        const float* f1b = g_f1n + ((size_t)(bb * N_ + m0)) * D_;
        const float* f2b = g_f2n + (size_t)bb * N_ * D_;
        for (int r = wid * 8; r < wid * 8 + 8; ++r) {
            const float4* a4 = (const float4*)(f1b + (size_t)r * D_);
            float4 a0 = a4[lane], a1 = a4[lane + 32];
#pragma unroll 2
            for (int c = 0; c < NC; ++c) {
                int col = topi[r * NC + c];
                const float4* b4 = (const float4*)(f2b + (size_t)col * D_);
                float4 b0 = b4[lane], b1 = b4[lane + 32];
                float s = a0.x * b0.x;
                s = fmaf(a0.y, b0.y, s);
                s = fmaf(a0.z, b0.z, s);
                s = fmaf(a0.w, b0.w, s);
                s = fmaf(a1.x, b1.x, s);
                s = fmaf(a1.y, b1.y, s);
                s = fmaf(a1.z, b1.z, s);
                s = fmaf(a1.w, b1.w, s);
#pragma unroll
                for (int o = 16; o; o >>= 1) s += __shfl_xor_sync(0xffffffffu, s, o);
                if (lane == 0) topv[r * NC + c] = s;   // overwrite with exact score
            }
        }
    }
    __syncthreads();

    // ---------------- final stable top-32 + softmax + scatter ----------------
    if (tid < TILE_M) {
        const int n = m0 + tid;
        const float* cv = topv + tid * NC;
        const int*   ci = topi + tid * NC;
        float tv[K_];
        int ti[K_];
#pragma unroll
        for (int k = 0; k < K_; k++) { tv[k] = -3.4e38f; ti[k] = 0x7fffffff; }
#pragma unroll
        for (int c = 0; c < NC; c++) {
            float v = cv[c];
            int idx = ci[c];
            float wv = tv[K_ - 1];
            if (v > wv || (v == wv && idx < ti[K_ - 1]))
                insert_final(tv, ti, v, idx);
        }
        float mx = tv[0];
        float e[K_];
        float s = 0.0f;
#pragma unroll
        for (int k = 0; k < K_; k++) { e[k] = expf((tv[k] - mx) * INV_T); s += e[k]; }
        float inv = 1.0f / s;
        size_t rowbase = ((size_t)bb * N_ + n) * N_;
        size_t idxbase = (size_t)B_ * N_ * N_ + ((size_t)bb * N_ + n) * K_;
#pragma unroll
        for (int k = 0; k < K_; k++) {
            out[rowbase + (size_t)ti[k]] = e[k] * inv;
            out[idxbase + k] = (float)ti[k];
        }
    }
}

// ---------------------------------------------------------------------------
extern "C" void kernel_launch(void* const* d_in, const int* in_sizes, int n_in,
                              void* d_out, int out_size) {
    const float* F1 = (const float*)d_in[0];
    const float* F2 = (const float*)d_in[1];
    float* out = (float*)d_out;

    cudaMemsetAsync(out, 0, (size_t)B_ * N_ * N_ * sizeof(float), 0);
    normalize_split_kernel<<<4096, 256>>>(F1, F2);

    cudaFuncSetAttribute(gemm_topk_hmma,
                         cudaFuncAttributeMaxDynamicSharedMemorySize, SMEM_TOTAL);
    gemm_topk_hmma<<<dim3(NCTILE, B_), 512, SMEM_TOTAL>>>(out);
}